// round 7
// baseline (speedup 1.0000x reference)
#include <cuda_runtime.h>
#include <cuda_fp16.h>
#include <string.h>

// Problem constants (fixed by the dataset)
#define NV 100000          // vertices (even)
#define TT 128             // temporal depth
#define NE 1600000         // edges
#define KK 9
#define CAP 128            // ELL bucket capacity (P(indeg+pad > 128) ~ 0 for Poisson(16))
#define OUT_CHUNKS 64

// Scratch (device globals; no allocation allowed). Row NV = zero dummy row.
__device__ __align__(16) __half g_h0[(size_t)(NV + 1) * TT];
__device__ __align__(16) __half g_h1[(size_t)(NV + 1) * TT];
__device__ int   g_cursor[NV];                            // degree counts after fill
__device__ __align__(16) int g_ell[(size_t)NV * CAP];     // 51.2 MB ELL neighbor lists
__device__ float g_part[TT * OUT_CHUNKS * 3];

// Bit-cast helpers (memcpy compiles away to a register move)
__device__ __forceinline__ unsigned int h2_bits(__half2 h) {
    unsigned int u; memcpy(&u, &h, 4); return u;
}
__device__ __forceinline__ __half2 bits_h2(unsigned int u) {
    __half2 h; memcpy(&h, &u, 4); return h;
}

// ---------------------------------------------------------------------------
// ELL build: zero cursors, scatter fill, pad each list to multiple of 4 with NV
// ---------------------------------------------------------------------------
__global__ void k_zero_cursor() {
    int i = blockIdx.x * blockDim.x + threadIdx.x;
    if (i < NV) g_cursor[i] = 0;
}

__global__ void __launch_bounds__(256) k_fill_ell(
    const int* __restrict__ src, const int* __restrict__ dst, int E)
{
    int i = (blockIdx.x * blockDim.x + threadIdx.x) * 4;
    if (i + 3 < E) {
        int4 s = *(const int4*)(src + i);
        int4 d = *(const int4*)(dst + i);
        int p0 = atomicAdd(&g_cursor[d.x], 1);
        int p1 = atomicAdd(&g_cursor[d.y], 1);
        int p2 = atomicAdd(&g_cursor[d.z], 1);
        int p3 = atomicAdd(&g_cursor[d.w], 1);
        if (p0 < CAP) g_ell[d.x * CAP + p0] = s.x;
        if (p1 < CAP) g_ell[d.y * CAP + p1] = s.y;
        if (p2 < CAP) g_ell[d.z * CAP + p2] = s.z;
        if (p3 < CAP) g_ell[d.w * CAP + p3] = s.w;
    } else {
        for (; i < E; i++) {
            int d = dst[i];
            int p = atomicAdd(&g_cursor[d], 1);
            if (p < CAP) g_ell[d * CAP + p] = src[i];
        }
    }
}

__global__ void k_pad_ell() {
    int i = blockIdx.x * blockDim.x + threadIdx.x;
    if (i >= NV) return;
    int d  = g_cursor[i];
    int dp = (d + 3) & ~3;
    if (dp > CAP) dp = CAP;
    for (int p = d; p < dp; p++) g_ell[i * CAP + p] = NV;   // dummy zero row
}

__global__ void k_zero_dummy() {
    int i = threadIdx.x;
    if (i < TT / 8) {
        uint4 z = make_uint4(0, 0, 0, 0);
        ((uint4*)(g_h0 + (size_t)NV * TT))[i] = z;
        ((uint4*)(g_h1 + (size_t)NV * TT))[i] = z;
    }
}

// ---------------------------------------------------------------------------
// Quantize external fp32 x -> half state (g_h0); 8 elems / thread
// ---------------------------------------------------------------------------
__global__ void __launch_bounds__(256) k_quant(const float* __restrict__ x) {
    int i = blockIdx.x * blockDim.x + threadIdx.x;   // one uint4 (8 halfs) per thread
    const int n8 = (NV * TT) / 8;                    // 1.6M
    if (i >= n8) return;
    float4 a = ((const float4*)x)[2 * i + 0];
    float4 b = ((const float4*)x)[2 * i + 1];
    uint4 o;
    o.x = h2_bits(__floats2half2_rn(a.x, a.y));
    o.y = h2_bits(__floats2half2_rn(a.z, a.w));
    o.z = h2_bits(__floats2half2_rn(b.x, b.y));
    o.w = h2_bits(__floats2half2_rn(b.z, b.w));
    ((uint4*)g_h0)[i] = o;
}

// ---------------------------------------------------------------------------
// Fused layer: 2 nodes per warp (16 lanes x 16B each), ELL gather with
// zero-row padding (branch-free inner loop), fp16 pairwise tree per 4
// neighbors -> fp32 accumulate, then conv1d(K=9) + bias + ReLU from smem.
//   mean_aggr(conv(x)+b) == conv(mean_aggr(x)) + b
// ---------------------------------------------------------------------------
__global__ void __launch_bounds__(256) k_agg_conv(
    int sel, const float* __restrict__ conv_w, const float* __restrict__ conv_b, int layer)
{
    const __half* xin  = (sel == 1) ? g_h1 : g_h0;
    __half*       xout = (sel == 1) ? g_h0 : g_h1;

    int warp = (blockIdx.x * blockDim.x + threadIdx.x) >> 5;   // 50000 warps
    int lane = threadIdx.x & 31;
    int half = lane >> 4;            // which node of the pair
    int sub  = lane & 15;            // 16 lanes per node, 16B each
    int node = warp * 2 + half;      // NV even; grid exact -> always < NV

    const uint4* __restrict__ x16 = (const uint4*)xin;    // row = 16 uint4 (256B)
    const int* __restrict__ nb = g_ell + (size_t)node * CAP;
    int deg  = g_cursor[node];
    int degp = (deg + 3) & ~3;       // padded with dummy-NV entries

    // self loop (fp32)
    float acc[8];
    {
        uint4 sv = x16[node * 16 + sub];
        float2 f0 = __half22float2(bits_h2(sv.x));
        float2 f1 = __half22float2(bits_h2(sv.y));
        float2 f2 = __half22float2(bits_h2(sv.z));
        float2 f3 = __half22float2(bits_h2(sv.w));
        acc[0] = f0.x; acc[1] = f0.y; acc[2] = f1.x; acc[3] = f1.y;
        acc[4] = f2.x; acc[5] = f2.y; acc[6] = f3.x; acc[7] = f3.y;
    }

    for (int j = 0; j < degp; j += 4) {
        int4 u = *(const int4*)(nb + j);          // broadcast within half-warp
        uint4 a = __ldg(&x16[u.x * 16 + sub]);
        uint4 b = __ldg(&x16[u.y * 16 + sub]);
        uint4 c = __ldg(&x16[u.z * 16 + sub]);
        uint4 d = __ldg(&x16[u.w * 16 + sub]);
        // fp16 pairwise tree (depth 2) per half2 slot, then fp32 add
        __half2 s0 = __hadd2(__hadd2(bits_h2(a.x), bits_h2(b.x)),
                             __hadd2(bits_h2(c.x), bits_h2(d.x)));
        __half2 s1 = __hadd2(__hadd2(bits_h2(a.y), bits_h2(b.y)),
                             __hadd2(bits_h2(c.y), bits_h2(d.y)));
        __half2 s2 = __hadd2(__hadd2(bits_h2(a.z), bits_h2(b.z)),
                             __hadd2(bits_h2(c.z), bits_h2(d.z)));
        __half2 s3 = __hadd2(__hadd2(bits_h2(a.w), bits_h2(b.w)),
                             __hadd2(bits_h2(c.w), bits_h2(d.w)));
        float2 f0 = __half22float2(s0);
        float2 f1 = __half22float2(s1);
        float2 f2 = __half22float2(s2);
        float2 f3 = __half22float2(s3);
        acc[0] += f0.x; acc[1] += f0.y; acc[2] += f1.x; acc[3] += f1.y;
        acc[4] += f2.x; acc[5] += f2.y; acc[6] += f3.x; acc[7] += f3.y;
    }

    float inv = 1.0f / (float)(deg + 1);   // cnt = indeg + 1 (self loop)
#pragma unroll
    for (int r = 0; r < 8; r++) acc[r] *= inv;

    // stage into smem (per node: 4 halo + 128 + 4 halo), conv in fp32
    __shared__ float smem[16][144];
    float* s = smem[(threadIdx.x >> 5) * 2 + half];
    if (sub < 4) { s[sub] = 0.0f; s[132 + sub] = 0.0f; }
    int t0 = sub * 8;
#pragma unroll
    for (int r = 0; r < 8; r++) s[4 + t0 + r] = acc[r];
    __syncwarp();

    float rw[16];
#pragma unroll
    for (int k = 0; k < 16; k++) rw[k] = s[t0 + k];

    float w[KK];
#pragma unroll
    for (int k = 0; k < KK; k++) w[k] = conv_w[layer * KK + k];
    float b = conv_b[layer];

    float o[8];
#pragma unroll
    for (int r = 0; r < 8; r++) {
        float sum = b;
#pragma unroll
        for (int k = 0; k < KK; k++) sum = fmaf(w[k], rw[r + k], sum);
        o[r] = fmaxf(sum, 0.0f);
    }
    uint4 ho;
    ho.x = h2_bits(__floats2half2_rn(o[0], o[1]));
    ho.y = h2_bits(__floats2half2_rn(o[2], o[3]));
    ho.z = h2_bits(__floats2half2_rn(o[4], o[5]));
    ho.w = h2_bits(__floats2half2_rn(o[6], o[7]));
    ((uint4*)xout)[node * 16 + sub] = ho;
}

// ---------------------------------------------------------------------------
// Readout: flat view of state (node-major == reference reshape order)
// ---------------------------------------------------------------------------
__global__ void __launch_bounds__(256) k_out_partial(const float* __restrict__ W) {
    int t  = blockIdx.y;
    int ch = blockIdx.x;
    const int NP = NV / 2;                            // 50000 half2 pairs per row
    const int chunk = (NP + OUT_CHUNKS - 1) / OUT_CHUNKS;  // 782
    int p0 = ch * chunk;
    int p1 = min(p0 + chunk, NP);

    const __half2* __restrict__ xr = (const __half2*)(g_h1 + (size_t)t * NV);
    const float2* __restrict__ W0 = (const float2*)W;
    const float2* __restrict__ W1 = (const float2*)(W + NV);
    const float2* __restrict__ W2 = (const float2*)(W + 2 * NV);

    float s0 = 0.f, s1 = 0.f, s2 = 0.f;
    for (int p = p0 + threadIdx.x; p < p1; p += 256) {
        float2 v  = __half22float2(xr[p]);
        float2 w0 = W0[p], w1 = W1[p], w2 = W2[p];
        s0 = fmaf(v.x, w0.x, fmaf(v.y, w0.y, s0));
        s1 = fmaf(v.x, w1.x, fmaf(v.y, w1.y, s1));
        s2 = fmaf(v.x, w2.x, fmaf(v.y, w2.y, s2));
    }
#pragma unroll
    for (int o = 16; o > 0; o >>= 1) {
        s0 += __shfl_down_sync(0xffffffffu, s0, o);
        s1 += __shfl_down_sync(0xffffffffu, s1, o);
        s2 += __shfl_down_sync(0xffffffffu, s2, o);
    }
    __shared__ float sw[8][3];
    int wid = threadIdx.x >> 5, lane = threadIdx.x & 31;
    if (lane == 0) { sw[wid][0] = s0; sw[wid][1] = s1; sw[wid][2] = s2; }
    __syncthreads();
    if (threadIdx.x < 3) {
        float tot = 0.f;
#pragma unroll
        for (int wq = 0; wq < 8; wq++) tot += sw[wq][threadIdx.x];
        g_part[(t * OUT_CHUNKS + ch) * 3 + threadIdx.x] = tot;
    }
}

__global__ void k_out_final(const float* __restrict__ b_out, float* __restrict__ out) {
    int t = blockIdx.x;
    if (threadIdx.x < 3) {
        float s = b_out[threadIdx.x];
        for (int ch = 0; ch < OUT_CHUNKS; ch++)
            s += g_part[(t * OUT_CHUNKS + ch) * 3 + threadIdx.x];
        out[t * 3 + threadIdx.x] = s;
    }
}

// ---------------------------------------------------------------------------
// Launch
// ---------------------------------------------------------------------------
extern "C" void kernel_launch(void* const* d_in, const int* in_sizes, int n_in,
                              void* d_out, int out_size) {
    const float* x      = (const float*)d_in[0];   // [N, T]
    const int*   eidx   = (const int*)  d_in[1];   // [2, E]
    const float* conv_w = (const float*)d_in[2];   // [L,1,1,K]
    const float* conv_b = (const float*)d_in[3];   // [L,1]
    const float* W_out  = (const float*)d_in[4];   // [3, N]
    const float* b_out  = (const float*)d_in[5];   // [3]
    float* out = (float*)d_out;                    // [T, 3]

    int E = in_sizes[1] / 2;
    const int* src = eidx;
    const int* dst = eidx + E;

    // ELL build + quantize x + dummy zero row
    k_zero_cursor<<<(NV + 255) / 256, 256>>>();
    k_zero_dummy<<<1, 32>>>();
    k_quant<<<((NV * TT / 8) + 255) / 256, 256>>>(x);
    k_fill_ell<<<((E / 4) + 255) / 256, 256>>>(src, dst, E);
    k_pad_ell<<<(NV + 255) / 256, 256>>>();

    // 3 fused layers: aggregate(mean) -> conv(K=9) -> +b -> relu
    const int agg_blocks = (NV / 2) / 8;   // 2 nodes/warp, 8 warps/block -> 6250 blocks
    k_agg_conv<<<agg_blocks, 256>>>(0, conv_w, conv_b, 0);   // h0 -> h1
    k_agg_conv<<<agg_blocks, 256>>>(1, conv_w, conv_b, 1);   // h1 -> h0
    k_agg_conv<<<agg_blocks, 256>>>(2, conv_w, conv_b, 2);   // h0 -> h1

    // Readout
    dim3 pg(OUT_CHUNKS, TT);
    k_out_partial<<<pg, 256>>>(W_out);
    k_out_final<<<TT, 32>>>(b_out, out);
}